// round 17
// baseline (speedup 1.0000x reference)
#include <cuda_runtime.h>
#include <cuda_fp16.h>
#include <math.h>
#include <stdint.h>

// ---------------------------------------------------------------------------
// Problem constants
// ---------------------------------------------------------------------------
#define BB 256      // batch
#define TT 128      // timesteps
#define HH 2048     // hidden
#define CC 10       // classes

// ---------------------------------------------------------------------------
// R17: fp16 W-split 2-term (D = h @ (Whi+Wlo)^T) with ldsm-optimal warp tile.
// CTA 64x64, 512 threads = 8 K-groups x 2 warps. Warp tile 64x32 (4mt x 4nt).
// Group g: K in [g*256,(g+1)*256), BK=32, 8 k-iters, 2-stage cp.async pipe,
// 64B XOR-swizzled rows. Warp w on SMSP w%4 -> each SMSP hosts warps of 4
// different groups (latency cover). R5's 2-barrier/iter rhythm.
// ---------------------------------------------------------------------------
#define BM 64
#define BN 64
#define BK 32
#define NGRP 8
#define KSPLIT (HH / NGRP)   // 256
#define NKT (KSPLIT / BK)    // 8
#define NTH 512

#define ROWB 64                          // 32 fp16 per row, XOR swizzled
#define BUFB (64 * ROWB)                 // one 64-row buffer: 4096 B
#define GSTAGE (3 * BUFB)                // A,Whi,Wlo: 12288 B
#define GPIPE (2 * GSTAGE)               // 24576 B (>= 16KB exchange)
#define SMEM_TOTAL (NGRP * GPIPE)        // 196608 B

#define SKEW_CYC 100                     // per-group phase offset (marginal+)

// ---------------------------------------------------------------------------
// Device-global scratch (allocation-free)
// ---------------------------------------------------------------------------
__device__ __half g_whi[HH * HH];
__device__ __half g_wlo[HH * HH];
__device__ __half g_h[2][BB * HH];

// ---------------------------------------------------------------------------
// PTX helpers (base-arch features only; nothing 'a'-gated)
// ---------------------------------------------------------------------------
__device__ __forceinline__ uint32_t smem_u32(const void* p) {
    uint32_t a;
    asm("{ .reg .u64 t; cvta.to.shared.u64 t, %1; cvt.u32.u64 %0, t; }"
        : "=r"(a) : "l"(p));
    return a;
}
__device__ __forceinline__ void cp16(uint32_t dst, const void* src) {
    asm volatile("cp.async.cg.shared.global [%0], [%1], 16;"
                 :: "r"(dst), "l"(src) : "memory");
}
__device__ __forceinline__ void cp_commit() {
    asm volatile("cp.async.commit_group;" ::: "memory");
}
__device__ __forceinline__ void cp_wait1() {
    asm volatile("cp.async.wait_group 1;" ::: "memory");
}
__device__ __forceinline__ void cp_wait0() {
    asm volatile("cp.async.wait_group 0;" ::: "memory");
}
__device__ __forceinline__ void barg(int id) {   // per-group barrier, 64 thr
    asm volatile("bar.sync %0, 64;" :: "r"(id) : "memory");
}
__device__ __forceinline__ void barall() {       // full CTA
    asm volatile("bar.sync 0, 512;" ::: "memory");
}
__device__ __forceinline__ void ldsm4(uint32_t* r, uint32_t addr) {
    asm volatile("ldmatrix.sync.aligned.m8n8.x4.shared.b16 {%0,%1,%2,%3}, [%4];"
                 : "=r"(r[0]), "=r"(r[1]), "=r"(r[2]), "=r"(r[3]) : "r"(addr));
}
__device__ __forceinline__ void mma_fp16(float* c, const uint32_t* a, const uint32_t* b) {
    asm volatile(
        "mma.sync.aligned.m16n8k16.row.col.f32.f16.f16.f32 "
        "{%0,%1,%2,%3}, {%4,%5,%6,%7}, {%8,%9}, {%0,%1,%2,%3};"
        : "+f"(c[0]), "+f"(c[1]), "+f"(c[2]), "+f"(c[3])
        : "r"(a[0]), "r"(a[1]), "r"(a[2]), "r"(a[3]), "r"(b[0]), "r"(b[1]));
}

// ---------------------------------------------------------------------------
// Prep kernels
// ---------------------------------------------------------------------------
__global__ void k_convert_w(const float* __restrict__ W) {
    int i = blockIdx.x * blockDim.x + threadIdx.x;
    if (i < HH * HH) {
        float w = W[i];
        __half hi = __float2half_rn(w);
        g_whi[i] = hi;
        g_wlo[i] = __float2half_rn(w - __half2float(hi));
    }
}
__global__ void k_init_h() {
    int i = blockIdx.x * blockDim.x + threadIdx.x;
    if (i < BB * HH) g_h[0][i] = __float2half_rn(0.0f);
}

// ---------------------------------------------------------------------------
// One RNN step: D = h @ (Whi + Wlo)^T  (fp16 W-split 2-term on HMMA)
// ---------------------------------------------------------------------------
__global__ __launch_bounds__(NTH, 1)
void rnn_step_hmma(const __half* __restrict__ h_in,
                   const float* __restrict__ x,
                   const float* __restrict__ U,
                   const float* __restrict__ bh,
                   __half* __restrict__ h_out,
                   float* __restrict__ fout,
                   int t, int is_last) {
    extern __shared__ __align__(128) char smem[];
    const uint32_t sbase = smem_u32(smem);

    const int tid  = threadIdx.x;
    const int lane = tid & 31;
    const int grp  = tid >> 6;           // 0..7 (K-group)
    const int wn   = (tid >> 5) & 1;     // warp within group: n-half
    const int gtid = tid & 63;
    const int n0 = blockIdx.x * BN;
    const int m0 = blockIdx.y * BM;

    // ---- per-group phase stagger (timing only) ----
    if (grp != 0) {
        const long long skew = (long long)grp * SKEW_CYC;
        const long long t0 = clock64();
        while (clock64() - t0 < skew) { }
    }

    const uint32_t gbase = sbase + (uint32_t)grp * GPIPE;
    const int kbase = grp * KSPLIT;

    // ---- cp.async mapping: per buffer 64 rows x 4 chunks(16B) = 256 chunks;
    //      64 threads -> 4 chunks each: q = gtid + i*64, row=q>>2, c=q&3 ----
    int srcoff[4];
    uint32_t dstoff[4];
    #pragma unroll
    for (int i = 0; i < 4; i++) {
        const int q = gtid + i * 64;
        const int row = q >> 2;
        const int c = q & 3;
        srcoff[i] = row * HH + c * 8;
        dstoff[i] = (uint32_t)(row * ROWB + ((c ^ ((row >> 1) & 3)) << 4));
    }

    const __half* gsrc[3];
    gsrc[0] = h_in  + (size_t)m0 * HH + kbase;
    gsrc[1] = g_whi + (size_t)n0 * HH + kbase;
    gsrc[2] = g_wlo + (size_t)n0 * HH + kbase;

    // ---- ldmatrix lane addressing (R6-verified 64B-row swizzle) ----
    const int a_row = (lane & 7) + 8 * ((lane >> 3) & 1);
    const int a_c   = lane >> 4;               // 0..1
    const int b_row = ((lane >> 4) << 3) + (lane & 7);
    const int b_c   = (lane >> 3) & 1;

    const int brow0 = wn * 32 + b_row;         // B tiles 0,1; +16 for 2,3
    const int brow1 = brow0 + 16;

    float acc[4][4][4];                        // [mt][nt][elem]
    #pragma unroll
    for (int i = 0; i < 4; i++)
        #pragma unroll
        for (int j = 0; j < 4; j++)
            #pragma unroll
            for (int e = 0; e < 4; e++) acc[i][j][e] = 0.0f;

    // ---- prologue: stage 0 ----
    #pragma unroll
    for (int bf = 0; bf < 3; bf++) {
        const uint32_t db = gbase + (uint32_t)(bf * BUFB);
        #pragma unroll
        for (int i = 0; i < 4; i++)
            cp16(db + dstoff[i], gsrc[bf] + srcoff[i]);
    }
    cp_commit();

    const int mybar = grp + 1;                 // named barriers 1..8

    for (int kt = 0; kt < NKT; kt++) {
        const int cur = kt & 1;
        if (kt + 1 < NKT) {
            const uint32_t so = (uint32_t)((kt + 1) & 1) * GSTAGE;
            const int kk = (kt + 1) * BK;
            #pragma unroll
            for (int bf = 0; bf < 3; bf++) {
                const uint32_t db = gbase + so + (uint32_t)(bf * BUFB);
                #pragma unroll
                for (int i = 0; i < 4; i++)
                    cp16(db + dstoff[i], gsrc[bf] + kk + srcoff[i]);
            }
            cp_commit();
            cp_wait1();
        } else {
            cp_wait0();
        }
        barg(mybar);

        const uint32_t sb = gbase + (uint32_t)cur * GSTAGE;
        #pragma unroll
        for (int kh = 0; kh < BK / 16; kh++) {
            // A fragments: 4 m16 tiles (full 64 rows)
            uint32_t afr[4][4];
            #pragma unroll
            for (int mt = 0; mt < 4; mt++) {
                const int ar = mt * 16 + a_row;
                const int ac = (kh * 2 + a_c) ^ ((ar >> 1) & 3);
                ldsm4(afr[mt], sb + (0 * BUFB) + (uint32_t)(ar * ROWB + (ac << 4)));
            }
            // B fragments: Whi + Wlo, tiles 0..3 (2 ldsm each)
            uint32_t bhi[8], blo[8];
            {
                const int bc0 = (kh * 2 + b_c) ^ ((brow0 >> 1) & 3);
                const int bc1 = (kh * 2 + b_c) ^ ((brow1 >> 1) & 3);
                ldsm4(bhi,     sb + (1 * BUFB) + (uint32_t)(brow0 * ROWB + (bc0 << 4)));
                ldsm4(bhi + 4, sb + (1 * BUFB) + (uint32_t)(brow1 * ROWB + (bc1 << 4)));
                ldsm4(blo,     sb + (2 * BUFB) + (uint32_t)(brow0 * ROWB + (bc0 << 4)));
                ldsm4(blo + 4, sb + (2 * BUFB) + (uint32_t)(brow1 * ROWB + (bc1 << 4)));
            }
            // 32 MMAs per kh: hi then lo per (mt,nt)
            #pragma unroll
            for (int mt = 0; mt < 4; mt++)
                #pragma unroll
                for (int nt = 0; nt < 4; nt++) {
                    mma_fp16(acc[mt][nt], afr[mt], bhi + 2 * nt);
                    mma_fp16(acc[mt][nt], afr[mt], blo + 2 * nt);
                }
        }
        barg(mybar);
    }

    // ---- publish acc into own (now dead) pipeline region ----
    // 32 float2 per thread: p = (mt*4+nt)*2 + eh
    {
        float2* exg = (float2*)(smem + grp * GPIPE);
        #pragma unroll
        for (int mt = 0; mt < 4; mt++)
            #pragma unroll
            for (int nt = 0; nt < 4; nt++) {
                const int p = (mt * 4 + nt) * 2;
                exg[p * 64 + gtid]       = make_float2(acc[mt][nt][0], acc[mt][nt][1]);
                exg[(p + 1) * 64 + gtid] = make_float2(acc[mt][nt][2], acc[mt][nt][3]);
            }
    }
    barall();

    // ---- distributed combine + epilogue: each thread 4 pairs (8 outputs) ----
    // pglob = grp*4 + p (0..31): mt = pglob>>3, nt = (pglob>>1)&3, eh = pglob&1
    // slot gtid -> publisher coords: wn=gtid>>5, qid=(gtid&31)>>2, rid=gtid&3
    {
        const int wn_c = gtid >> 5;
        const int qid  = (gtid & 31) >> 2;
        const int rid  = gtid & 3;

        #pragma unroll
        for (int p = 0; p < 4; p++) {
            const int pglob = grp * 4 + p;
            const int mt = pglob >> 3;
            const int nt = (pglob >> 1) & 3;
            const int eh = pglob & 1;
            const int row = m0 + mt * 16 + eh * 8 + qid;
            const int j   = n0 + wn_c * 32 + nt * 8 + rid * 2;
            const float xb = x[(size_t)row * TT + t];

            float sx = 0.0f, sy = 0.0f;
            #pragma unroll
            for (int g = 0; g < NGRP; g++) {
                float2 v = ((float2*)(smem + g * GPIPE))[pglob * 64 + gtid];
                sx += v.x; sy += v.y;
            }
            const float v0 = tanhf(sx + xb * U[j]     + bh[j]);
            const float v1 = tanhf(sy + xb * U[j + 1] + bh[j + 1]);

            __half hh0 = __float2half_rn(v0);
            __half hh1 = __float2half_rn(v1);
            unsigned short s0 = *(unsigned short*)&hh0;
            unsigned short s1 = *(unsigned short*)&hh1;
            *(uint32_t*)(h_out + (size_t)row * HH + j) = (uint32_t)s0 | ((uint32_t)s1 << 16);
            if (is_last) {
                fout[(size_t)row * HH + j]     = v0;
                fout[(size_t)row * HH + j + 1] = v1;
            }
        }
    }
}

// ---------------------------------------------------------------------------
// Head: out[b,c] = sum_k h[b,k]*V[c,k] + bp[c]
// One block per batch row, one warp per class; shfl reduction.
// ---------------------------------------------------------------------------
__global__ __launch_bounds__(320)
void rnn_head_kernel(const float* __restrict__ h,
                     const float* __restrict__ V,
                     const float* __restrict__ bp,
                     float* __restrict__ out) {
    const int b = blockIdx.x;
    const int c = threadIdx.x >> 5;      // 0..9
    const int lane = threadIdx.x & 31;

    const float* hrow = h + (size_t)b * HH;
    const float* vrow = V + (size_t)c * HH;

    float s = 0.0f;
    #pragma unroll 16
    for (int k = lane; k < HH; k += 32)
        s = fmaf(hrow[k], vrow[k], s);

    #pragma unroll
    for (int o = 16; o > 0; o >>= 1)
        s += __shfl_down_sync(0xFFFFFFFF, s, o);

    if (lane == 0) out[(size_t)b * CC + c] = s + bp[c];
}

// ---------------------------------------------------------------------------
// Host launch
// ---------------------------------------------------------------------------
extern "C" void kernel_launch(void* const* d_in, const int* in_sizes, int n_in,
                              void* d_out, int out_size) {
    const float* x  = (const float*)d_in[0];   // [B, T]
    const float* U  = (const float*)d_in[1];   // [H, 1]
    const float* W  = (const float*)d_in[2];   // [H, H]
    const float* V  = (const float*)d_in[3];   // [C, H]
    const float* bh = (const float*)d_in[4];   // [H]
    const float* bp = (const float*)d_in[5];   // [C]
    float* out = (float*)d_out;                // [B*H + B*C]

    cudaFuncSetAttribute(rnn_step_hmma,
                         cudaFuncAttributeMaxDynamicSharedMemorySize, SMEM_TOTAL);

    void* p_h;
    cudaGetSymbolAddress(&p_h, g_h);
    __half* hbuf = (__half*)p_h;

    // prep: split W into fp16 hi/lo (exact pair), zero h0
    k_convert_w<<<(HH * HH + 255) / 256, 256>>>(W);
    k_init_h<<<(BB * HH + 255) / 256, 256>>>();

    // 128 sequential steps, ping-pong fp16 hidden state
    dim3 grid(HH / BN, BB / BM);  // (32, 4) = 128 CTAs
    for (int t = 0; t < TT; t++) {
        const int inb  = t & 1;
        const int outb = inb ^ 1;
        rnn_step_hmma<<<grid, NTH, SMEM_TOTAL>>>(
            hbuf + (size_t)inb * BB * HH,
            x, U, bh,
            hbuf + (size_t)outb * BB * HH,
            out, t, (t == TT - 1) ? 1 : 0);
    }

    // head on fp32 h_last (written into d_out by last step)
    rnn_head_kernel<<<BB, 320>>>(out, V, bp, out + (size_t)BB * HH);
}